// round 3
// baseline (speedup 1.0000x reference)
#include <cuda_runtime.h>
#include <cuda_bf16.h>
#include <math.h>

#define T_STEPS 64
#define B_SZ    64
#define H_SZ    256
#define G_SZ    1024
#define M_TOT   4096      // T*B
#define V_SZ    32000

// ---------------- scratch (static device allocations are allowed) ----------
__device__ __align__(256) float g_bufA[M_TOT * H_SZ];
__device__ __align__(256) float g_bufB[M_TOT * H_SZ];
__device__ __align__(256) float g_gx[M_TOT * G_SZ];
__device__ __align__(256) float g_hinit[B_SZ * H_SZ];
__device__ __align__(256) float g_hfin[3 * B_SZ * H_SZ];
__device__ __align__(256) float g_cfin[3 * B_SZ * H_SZ];

// ---------------- software grid barrier ------------------------------------
__device__ volatile unsigned g_bar_gen;
__device__ unsigned g_bar_cnt;

// ---------------- embedding -------------------------------------------------
// Tokens are int32 (JAX x64 disabled downgrades int64 -> int32).
__global__ void embed_k(const int* __restrict__ tok,
                        const float* __restrict__ emb,
                        float* __restrict__ out, int dec)
{
    int row = blockIdx.x;            // row = t*B + b
    int tid = threadIdx.x;           // 256 threads = H
    int t;
    if (dec) t = (row < B_SZ) ? 0 : tok[row - B_SZ];
    else     t = tok[row];
    out[row * H_SZ + tid] = emb[(size_t)t * H_SZ + tid];
}

// ---------------- h-init materialization ------------------------------------
__global__ void inith_k(const float* __restrict__ src, float* __restrict__ dst, int bcast)
{
    int b = blockIdx.x, k = threadIdx.x;
    dst[b * H_SZ + k] = bcast ? src[k] : src[b * H_SZ + k];
}

// ---------------- fp32 GEMM: C[M,N] = A[M,256] * W[N,256]^T + b1 (+ b2) -----
// BM=BN=64, BK=16, 256 threads, 4x4 thread tiles.
__global__ void __launch_bounds__(256) gemm256(
    const float* __restrict__ A, const float* __restrict__ W,
    const float* __restrict__ b1, const float* __restrict__ b2,
    float* __restrict__ C, int M, int N)
{
    __shared__ float As[16][68];
    __shared__ float Ws[16][68];

    int tid = threadIdx.x;
    int tx = tid & 15, ty = tid >> 4;
    int n0 = blockIdx.x * 64, m0 = blockIdx.y * 64;

    int lm = tid >> 2;           // 0..63
    int lk = (tid & 3) * 4;      // 0,4,8,12

    float acc[4][4];
#pragma unroll
    for (int i = 0; i < 4; i++)
#pragma unroll
        for (int j = 0; j < 4; j++) acc[i][j] = 0.f;

    const float* Ap = A + (size_t)(m0 + lm) * 256 + lk;
    const float* Wp = W + (size_t)(n0 + lm) * 256 + lk;

    for (int kc = 0; kc < 256; kc += 16) {
        float4 av = *(const float4*)(Ap + kc);
        float4 wv = *(const float4*)(Wp + kc);
        __syncthreads();
        As[lk + 0][lm] = av.x; As[lk + 1][lm] = av.y;
        As[lk + 2][lm] = av.z; As[lk + 3][lm] = av.w;
        Ws[lk + 0][lm] = wv.x; Ws[lk + 1][lm] = wv.y;
        Ws[lk + 2][lm] = wv.z; Ws[lk + 3][lm] = wv.w;
        __syncthreads();
#pragma unroll
        for (int k = 0; k < 16; k++) {
            float4 a = *(const float4*)&As[k][ty * 4];
            float4 w = *(const float4*)&Ws[k][tx * 4];
            acc[0][0] += a.x * w.x; acc[0][1] += a.x * w.y; acc[0][2] += a.x * w.z; acc[0][3] += a.x * w.w;
            acc[1][0] += a.y * w.x; acc[1][1] += a.y * w.y; acc[1][2] += a.y * w.z; acc[1][3] += a.y * w.w;
            acc[2][0] += a.z * w.x; acc[2][1] += a.z * w.y; acc[2][2] += a.z * w.z; acc[2][3] += a.z * w.w;
            acc[3][0] += a.w * w.x; acc[3][1] += a.w * w.y; acc[3][2] += a.w * w.z; acc[3][3] += a.w * w.w;
        }
    }

    float bias[4];
#pragma unroll
    for (int j = 0; j < 4; j++) {
        int n = n0 + tx * 4 + j;
        float bb = b1 ? b1[n] : 0.f;
        if (b2) bb += b2[n];
        bias[j] = bb;
    }
#pragma unroll
    for (int i = 0; i < 4; i++) {
        size_t r = (size_t)(m0 + ty * 4 + i) * N + n0 + tx * 4;
#pragma unroll
        for (int j = 0; j < 4; j++)
            C[r + j] = acc[i][j] + bias[j];
    }
}

// ---------------- persistent recurrence -------------------------------------
// grid = 128 CTAs x 256 threads. CTA j owns hidden cols {2j, 2j+1} (8 gate rows).
// smem: hs[64][260] staged h, Wsl[8][256] Whh slice, gb[4][64][2] gate exchange.
#define REC_SMEM_BYTES ((64 * 260 + 8 * 256 + 4 * 64 * 2) * 4)

__device__ __forceinline__ float sigf(float x) { return 1.f / (1.f + expf(-x)); }

__global__ void __launch_bounds__(256) rec_k(
    const float* __restrict__ Gx, const float* __restrict__ Whh,
    const float* __restrict__ hinit, const float* __restrict__ cinit, int cbcast,
    float* __restrict__ Xout, float* __restrict__ hfin, float* __restrict__ cfin)
{
    extern __shared__ float sm[];
    float* hs  = sm;                 // [64][260]
    float* Wsl = sm + 64 * 260;      // [8][256]
    float* gb  = Wsl + 8 * 256;      // [4][64][2]

    int tid = threadIdx.x, bx = blockIdx.x;
    int b = tid & 63, q = tid >> 6;

    // load Whh slice: rows q*256 + 2*bx + p  -> local row 2q+p
#pragma unroll
    for (int v = 0; v < 2; v++) {
        int id = tid + 256 * v;        // float4 id 0..511
        int lr = id >> 6, k4 = id & 63;
        int qq = lr >> 1, p = lr & 1;
        int grow = qq * 256 + 2 * bx + p;
        float4 w = *(const float4*)(Whh + (size_t)grow * 256 + 4 * k4);
        *(float4*)&Wsl[lr * 256 + 4 * k4] = w;
    }

    float creg = 0.f, hlast = 0.f;
    int p_ = tid >> 6;               // valid for tid<128: p in {0,1}
    int colp = 2 * bx + (p_ & 1);
    if (tid < 128)
        creg = cbcast ? cinit[colp] : cinit[b * H_SZ + colp];
    __syncthreads();

    for (int t = 0; t < T_STEPS; t++) {
        const float* hsrc = (t == 0) ? hinit : (Xout + (size_t)(t - 1) * B_SZ * H_SZ);
        // stage h [64][256] -> smem padded [b][260]
#pragma unroll
        for (int v = 0; v < 16; v++) {
            int id = tid + 256 * v;
            int bb = id >> 6, k4 = id & 63;
            float4 hv = __ldcg((const float4*)(hsrc + bb * 256 + 4 * k4));
            *(float4*)&hs[bb * 260 + 4 * k4] = hv;
        }
        float gx0 = Gx[(size_t)(t * 64 + b) * 1024 + q * 256 + 2 * bx];
        float gx1 = Gx[(size_t)(t * 64 + b) * 1024 + q * 256 + 2 * bx + 1];
        __syncthreads();

        const float* hrow = hs + b * 260;
        const float* w0 = Wsl + (2 * q) * 256;
        const float* w1 = w0 + 256;
        float s00 = 0.f, s01 = 0.f, s10 = 0.f, s11 = 0.f;
#pragma unroll 8
        for (int k4 = 0; k4 < 64; k4++) {
            float4 hv = *(const float4*)(hrow + 4 * k4);
            float4 a  = *(const float4*)(w0 + 4 * k4);
            float4 c2 = *(const float4*)(w1 + 4 * k4);
            s00 += hv.x * a.x;  s00 += hv.y * a.y;
            s01 += hv.z * a.z;  s01 += hv.w * a.w;
            s10 += hv.x * c2.x; s10 += hv.y * c2.y;
            s11 += hv.z * c2.z; s11 += hv.w * c2.w;
        }
        gb[q * 128 + b * 2 + 0] = gx0 + s00 + s01;
        gb[q * 128 + b * 2 + 1] = gx1 + s10 + s11;
        __syncthreads();

        if (tid < 128) {
            int p = tid >> 6;
            float iv = gb[0 * 128 + b * 2 + p];
            float fv = gb[1 * 128 + b * 2 + p];
            float gv = gb[2 * 128 + b * 2 + p];
            float ov = gb[3 * 128 + b * 2 + p];
            float cn = sigf(fv) * creg + sigf(iv) * tanhf(gv);
            float hn = sigf(ov) * tanhf(cn);
            creg = cn; hlast = hn;
            Xout[(size_t)(t * 64 + b) * 256 + 2 * bx + p] = hn;
        }

        // grid barrier
        __syncthreads();
        __threadfence();
        if (tid == 0) {
            unsigned g = g_bar_gen;
            if (atomicAdd(&g_bar_cnt, 1u) == 127u) {
                g_bar_cnt = 0;
                __threadfence();
                g_bar_gen = g + 1;
            } else {
                while (g_bar_gen == g) { }
            }
        }
        __syncthreads();
    }

    if (tid < 128) {
        int p = tid >> 6;
        cfin[b * H_SZ + 2 * bx + p] = creg;
        hfin[b * H_SZ + 2 * bx + p] = hlast;
    }
}

// ---------------- row argmax over V ----------------------------------------
__global__ void argmax_k(const float* __restrict__ logits, float* __restrict__ outIdx)
{
    int m = blockIdx.x;
    const float* row = logits + (size_t)m * V_SZ;
    int tid = threadIdx.x;
    float bv = -__int_as_float(0x7f800000);  // -inf
    int bi = 0;
    for (int n = tid; n < V_SZ; n += 256) {
        float v = row[n];
        if (v > bv) { bv = v; bi = n; }
    }
    __shared__ float sv[256];
    __shared__ int   si[256];
    sv[tid] = bv; si[tid] = bi;
    __syncthreads();
    for (int s = 128; s > 0; s >>= 1) {
        if (tid < s) {
            float ov = sv[tid + s]; int oi = si[tid + s];
            if (ov > sv[tid] || (ov == sv[tid] && oi < si[tid])) { sv[tid] = ov; si[tid] = oi; }
        }
        __syncthreads();
    }
    if (tid == 0) outIdx[m] = (float)si[0];
}

// ---------------- launch ----------------------------------------------------
extern "C" void kernel_launch(void* const* d_in, const int* in_sizes, int n_in,
                              void* d_out, int out_size)
{
    const int* inputs  = (const int*)d_in[0];
    const int* targets = (const int*)d_in[1];
    const float* enc_emb = (const float*)d_in[2];
    const float* enc_Wih = (const float*)d_in[3];
    const float* enc_Whh = (const float*)d_in[4];
    const float* enc_bih = (const float*)d_in[5];
    const float* enc_bhh = (const float*)d_in[6];
    const float* hidden0 = (const float*)d_in[7];
    const float* cell0   = (const float*)d_in[8];
    const float* dec_emb = (const float*)d_in[9];
    const float* dec_Wih = (const float*)d_in[10];
    const float* dec_Whh = (const float*)d_in[11];
    const float* dec_bih = (const float*)d_in[12];
    const float* dec_bhh = (const float*)d_in[13];
    const float* fc_W    = (const float*)d_in[14];
    const float* fc_b    = (const float*)d_in[15];
    float* out = (float*)d_out;

    float *bufA, *bufB, *gx, *hin, *hfin, *cfin;
    cudaGetSymbolAddress((void**)&bufA, g_bufA);
    cudaGetSymbolAddress((void**)&bufB, g_bufB);
    cudaGetSymbolAddress((void**)&gx,   g_gx);
    cudaGetSymbolAddress((void**)&hin,  g_hinit);
    cudaGetSymbolAddress((void**)&hfin, g_hfin);
    cudaGetSymbolAddress((void**)&cfin, g_cfin);

    cudaFuncSetAttribute(rec_k, cudaFuncAttributeMaxDynamicSharedMemorySize, REC_SMEM_BYTES);

    float* cur = bufA;
    float* nxt = bufB;

    // ---- encoder ----
    embed_k<<<M_TOT, 256>>>(inputs, enc_emb, cur, 0);
    for (int l = 0; l < 3; l++) {
        gemm256<<<dim3(16, 64), 256>>>(cur, enc_Wih + (size_t)l * G_SZ * H_SZ,
                                       enc_bih + l * G_SZ, enc_bhh + l * G_SZ,
                                       gx, M_TOT, G_SZ);
        inith_k<<<B_SZ, 256>>>(hidden0 + l * H_SZ, hin, 1);
        rec_k<<<128, 256, REC_SMEM_BYTES>>>(gx, enc_Whh + (size_t)l * G_SZ * H_SZ,
                                            hin, cell0 + l * H_SZ, 1,
                                            nxt, hfin + (size_t)l * B_SZ * H_SZ,
                                            cfin + (size_t)l * B_SZ * H_SZ);
        float* tmp = cur; cur = nxt; nxt = tmp;
    }

    // ---- decoder (teacher forcing, shifted targets) ----
    embed_k<<<M_TOT, 256>>>(targets, dec_emb, cur, 1);
    for (int l = 0; l < 3; l++) {
        gemm256<<<dim3(16, 64), 256>>>(cur, dec_Wih + (size_t)l * G_SZ * H_SZ,
                                       dec_bih + l * G_SZ, dec_bhh + l * G_SZ,
                                       gx, M_TOT, G_SZ);
        inith_k<<<B_SZ, 256>>>(hfin + (size_t)l * B_SZ * H_SZ, hin, 0);
        rec_k<<<128, 256, REC_SMEM_BYTES>>>(gx, dec_Whh + (size_t)l * G_SZ * H_SZ,
                                            hin, cfin + (size_t)l * B_SZ * H_SZ, 0,
                                            nxt, hfin + (size_t)l * B_SZ * H_SZ,
                                            cfin + (size_t)l * B_SZ * H_SZ);
        float* tmp = cur; cur = nxt; nxt = tmp;
    }

    // ---- FC projection to vocab ----
    gemm256<<<dim3(V_SZ / 64, M_TOT / 64), 256>>>(cur, fc_W, fc_b, (const float*)nullptr,
                                                  out, M_TOT, V_SZ);

    // ---- predicted words (tail of output, if present) ----
    long long need = (long long)M_TOT * V_SZ + M_TOT;
    if ((long long)out_size >= need)
        argmax_k<<<M_TOT, 256>>>(out, out + (size_t)M_TOT * V_SZ);
}

// round 6
// speedup vs baseline: 1.3985x; 1.3985x over previous
#include <cuda_runtime.h>
#include <cuda_bf16.h>
#include <math.h>
#include <stdint.h>

#define T_STEPS 64
#define B_SZ    64
#define H_SZ    256
#define G_SZ    1024
#define M_TOT   4096      // T*B
#define V_SZ    32000

// ---------------- scratch ----------------------------------------------------
__device__ __align__(256) float g_bufA[M_TOT * H_SZ];
__device__ __align__(256) float g_bufB[M_TOT * H_SZ];
__device__ __align__(256) float g_gx[M_TOT * G_SZ];
__device__ __align__(256) float g_hinit[B_SZ * H_SZ];
__device__ __align__(256) float g_hfin[3 * B_SZ * H_SZ];
__device__ __align__(256) float g_cfin[3 * B_SZ * H_SZ];

// ---------------- software grid barrier --------------------------------------
__device__ volatile unsigned g_bar_gen;
__device__ unsigned g_bar_cnt;

// ================= bf16 2-split helpers ======================================
__device__ __forceinline__ uint32_t pack_bf2(unsigned short lo, unsigned short hi) {
    return ((uint32_t)hi << 16) | (uint32_t)lo;
}
__device__ __forceinline__ void split_bf(float a, unsigned short& h, unsigned short& l) {
    __nv_bfloat16 hb = __float2bfloat16_rn(a);
    float hf = __bfloat162float(hb);
    __nv_bfloat16 lb = __float2bfloat16_rn(a - hf);
    h = __bfloat16_as_ushort(hb);
    l = __bfloat16_as_ushort(lb);
}
// split a float4 (4 consecutive k) into hi/lo packed bf16x2 pairs, store as uint2
__device__ __forceinline__ void split_store4(unsigned short* dhi, unsigned short* dlo, float4 a) {
    unsigned short h0, h1, h2, h3, l0, l1, l2, l3;
    split_bf(a.x, h0, l0); split_bf(a.y, h1, l1);
    split_bf(a.z, h2, l2); split_bf(a.w, h3, l3);
    uint2 hv; hv.x = pack_bf2(h0, h1); hv.y = pack_bf2(h2, h3);
    uint2 lv; lv.x = pack_bf2(l0, l1); lv.y = pack_bf2(l2, l3);
    *(uint2*)dhi = hv;
    *(uint2*)dlo = lv;
}

#define MMA_BF16(c, a, b) \
    asm volatile("mma.sync.aligned.m16n8k16.row.col.f32.bf16.bf16.f32 " \
        "{%0,%1,%2,%3}, {%4,%5,%6,%7}, {%8,%9}, {%0,%1,%2,%3};" \
        : "+f"((c)[0]), "+f"((c)[1]), "+f"((c)[2]), "+f"((c)[3]) \
        : "r"((a)[0]), "r"((a)[1]), "r"((a)[2]), "r"((a)[3]), \
          "r"((b)[0]), "r"((b)[1]))

// ================= bf16 2-split mma.sync GEMM ================================
// C[4096, Ntot] = A[4096,256] @ W[Ntot,256]^T + b1 (+ b2)
// CTA tile 128x64, full K=256 resident, 8 warps as 4(M) x 2(N), warp tile 32x32.
#define BG_LD   264                       // halves per row (256 + 8 pad)
#define BG_AHI  0
#define BG_ALO  (128 * BG_LD)             // half-index offsets
#define BG_BHI  (2 * 128 * BG_LD)
#define BG_BLO  (2 * 128 * BG_LD + 64 * BG_LD)
#define BG_SMEM ((2 * 128 * BG_LD + 2 * 64 * BG_LD) * 2)   // 202752 bytes

__global__ void __launch_bounds__(256, 1) bgemm(
    const float* __restrict__ A, const float* __restrict__ W,
    const float* __restrict__ b1, const float* __restrict__ b2,
    float* __restrict__ C, int Ntot)
{
    extern __shared__ __align__(16) unsigned short bsm[];

    int tid = threadIdx.x;
    int wid = tid >> 5, lane = tid & 31;
    int g = lane >> 2, t = lane & 3;
    int warpM = wid >> 1, warpN = wid & 1;

    int nN = Ntot >> 6;          // N tiles
    int NT = nN << 5;            // total tiles (32 m-tiles)
    int per = (NT + gridDim.x - 1) / gridDim.x;
    int tau0 = blockIdx.x * per;
    int tau1 = tau0 + per; if (tau1 > NT) tau1 = NT;
    int mPrev = -1;

    for (int tau = tau0; tau < tau1; tau++) {
        int mT = tau / nN, nT = tau - mT * nN;
        int m0 = mT << 7, n0 = nT << 6;

        __syncthreads();
        if (mT != mPrev) {
            const float* Ap = A + (size_t)m0 * 256;
#pragma unroll
            for (int v = 0; v < 32; v++) {
                int id = tid + 256 * v;          // 8192 float4s = 128 x 64
                int r = id >> 6, c4 = (id & 63) * 4;
                float4 a = __ldg((const float4*)(Ap + (size_t)r * 256 + c4));
                int hidx = r * BG_LD + c4;
                split_store4(bsm + BG_AHI + hidx, bsm + BG_ALO + hidx, a);
            }
            mPrev = mT;
        }
        {
            const float* Wp = W + (size_t)n0 * 256;
#pragma unroll
            for (int v = 0; v < 16; v++) {
                int id = tid + 256 * v;          // 4096 float4s = 64 x 64
                int r = id >> 6, c4 = (id & 63) * 4;
                float4 a = __ldg((const float4*)(Wp + (size_t)r * 256 + c4));
                int hidx = r * BG_LD + c4;
                split_store4(bsm + BG_BHI + hidx, bsm + BG_BLO + hidx, a);
            }
        }
        __syncthreads();

        float acc[2][4][4];
#pragma unroll
        for (int i = 0; i < 2; i++)
#pragma unroll
            for (int j = 0; j < 4; j++)
#pragma unroll
                for (int k = 0; k < 4; k++) acc[i][j][k] = 0.f;

        int aRow = warpM * 32;
        int bRow = warpN * 32;

#pragma unroll 4
        for (int kk = 0; kk < 256; kk += 16) {
            uint32_t ah[2][4], al[2][4];
#pragma unroll
            for (int ms = 0; ms < 2; ms++) {
                int r0 = aRow + ms * 16 + g;
                int i00 = r0 * BG_LD + 2 * t + kk;
                int i10 = (r0 + 8) * BG_LD + 2 * t + kk;
                ah[ms][0] = *(const uint32_t*)(bsm + BG_AHI + i00);
                ah[ms][1] = *(const uint32_t*)(bsm + BG_AHI + i10);
                ah[ms][2] = *(const uint32_t*)(bsm + BG_AHI + i00 + 8);
                ah[ms][3] = *(const uint32_t*)(bsm + BG_AHI + i10 + 8);
                al[ms][0] = *(const uint32_t*)(bsm + BG_ALO + i00);
                al[ms][1] = *(const uint32_t*)(bsm + BG_ALO + i10);
                al[ms][2] = *(const uint32_t*)(bsm + BG_ALO + i00 + 8);
                al[ms][3] = *(const uint32_t*)(bsm + BG_ALO + i10 + 8);
            }
            uint32_t bh[4][2], bl[4][2];
#pragma unroll
            for (int ns = 0; ns < 4; ns++) {
                int rw = bRow + ns * 8 + g;
                int ib = rw * BG_LD + 2 * t + kk;
                bh[ns][0] = *(const uint32_t*)(bsm + BG_BHI + ib);
                bh[ns][1] = *(const uint32_t*)(bsm + BG_BHI + ib + 8);
                bl[ns][0] = *(const uint32_t*)(bsm + BG_BLO + ib);
                bl[ns][1] = *(const uint32_t*)(bsm + BG_BLO + ib + 8);
            }
#pragma unroll
            for (int ms = 0; ms < 2; ms++)
#pragma unroll
                for (int ns = 0; ns < 4; ns++) {
                    MMA_BF16(acc[ms][ns], ah[ms], bh[ns]);
                    MMA_BF16(acc[ms][ns], ah[ms], bl[ns]);
                    MMA_BF16(acc[ms][ns], al[ms], bh[ns]);
                }
        }

        // epilogue
#pragma unroll
        for (int ms = 0; ms < 2; ms++) {
            int row0 = m0 + aRow + ms * 16 + g;
#pragma unroll
            for (int ns = 0; ns < 4; ns++) {
                int col = n0 + bRow + ns * 8 + 2 * t;
                float bv0 = __ldg(b1 + col), bv1 = __ldg(b1 + col + 1);
                if (b2) { bv0 += __ldg(b2 + col); bv1 += __ldg(b2 + col + 1); }
                float2 o0, o1;
                o0.x = acc[ms][ns][0] + bv0; o0.y = acc[ms][ns][1] + bv1;
                o1.x = acc[ms][ns][2] + bv0; o1.y = acc[ms][ns][3] + bv1;
                *(float2*)(C + (size_t)row0 * Ntot + col) = o0;
                *(float2*)(C + (size_t)(row0 + 8) * Ntot + col) = o1;
            }
        }
    }
}

// ---------------- embedding --------------------------------------------------
__global__ void embed_k(const int* __restrict__ tok,
                        const float* __restrict__ emb,
                        float* __restrict__ out, int dec)
{
    int row = blockIdx.x;
    int tid = threadIdx.x;
    int t;
    if (dec) t = (row < B_SZ) ? 0 : tok[row - B_SZ];
    else     t = tok[row];
    out[row * H_SZ + tid] = emb[(size_t)t * H_SZ + tid];
}

// ---------------- h-init -----------------------------------------------------
__global__ void inith_k(const float* __restrict__ src, float* __restrict__ dst, int bcast)
{
    int b = blockIdx.x, k = threadIdx.x;
    dst[b * H_SZ + k] = bcast ? src[k] : src[b * H_SZ + k];
}

// ---------------- persistent recurrence --------------------------------------
// 128 CTAs x 256 threads; CTA j owns hidden cols {2j, 2j+1}.
// smem: hsT: float4[64 k4][65 pad] transposed h; Wsl[8][256]; gb[4][64][2].
#define REC_HST_F4   (64 * 65)                     // float4 count
#define REC_SMEM_BYTES (REC_HST_F4 * 16 + 8 * 256 * 4 + 4 * 64 * 2 * 4)

__device__ __forceinline__ float sigf(float x)   { return __fdividef(1.f, 1.f + __expf(-x)); }
__device__ __forceinline__ float tanh_f(float x) { float e = __expf(2.f * x); return __fdividef(e - 1.f, e + 1.f); }

__global__ void __launch_bounds__(256) rec_k(
    const float* __restrict__ Gx, const float* __restrict__ Whh,
    const float* __restrict__ hinit, const float* __restrict__ cinit, int cbcast,
    float* __restrict__ Xout, float* __restrict__ hfin, float* __restrict__ cfin)
{
    extern __shared__ float sm[];
    float4* hsT = (float4*)sm;                    // [k4][b] stride 65
    float*  Wsl = sm + REC_HST_F4 * 4;            // [8][256]
    float*  gb  = Wsl + 8 * 256;                  // [4][64][2]

    int tid = threadIdx.x, bx = blockIdx.x;
    int b = tid & 63, q = tid >> 6;

    // load Whh slice: rows q*256 + 2*bx + p  -> local row 2q+p
#pragma unroll
    for (int v = 0; v < 2; v++) {
        int id = tid + 256 * v;        // float4 id 0..511
        int lr = id >> 6, k4 = id & 63;
        int qq = lr >> 1, p = lr & 1;
        int grow = qq * 256 + 2 * bx + p;
        float4 w = *(const float4*)(Whh + (size_t)grow * 256 + 4 * k4);
        *(float4*)&Wsl[lr * 256 + 4 * k4] = w;
    }

    float creg = 0.f, hlast = 0.f;
    int p_ = tid >> 6;
    int colp = 2 * bx + (p_ & 1);
    if (tid < 128)
        creg = cbcast ? cinit[colp] : cinit[b * H_SZ + colp];
    __syncthreads();

    for (int t = 0; t < T_STEPS; t++) {
        const float* hsrc = (t == 0) ? hinit : (Xout + (size_t)(t - 1) * B_SZ * H_SZ);
        // stage h [64 b][256 k] -> transposed smem hsT[k4][b] (stride 65, conflict-free)
#pragma unroll
        for (int v = 0; v < 16; v++) {
            int id = tid + 256 * v;
            int bb = id >> 6, k4 = id & 63;
            float4 hv = __ldcg((const float4*)(hsrc + bb * 256 + 4 * k4));
            hsT[k4 * 65 + bb] = hv;
        }
        float gx0 = Gx[(size_t)(t * 64 + b) * 1024 + q * 256 + 2 * bx];
        float gx1 = Gx[(size_t)(t * 64 + b) * 1024 + q * 256 + 2 * bx + 1];
        __syncthreads();

        const float* w0 = Wsl + (2 * q) * 256;
        const float* w1 = w0 + 256;
        float s0 = 0.f, s1 = 0.f;
#pragma unroll 8
        for (int k4 = 0; k4 < 64; k4++) {
            float4 hv = hsT[k4 * 65 + b];
            float4 a  = *(const float4*)(w0 + 4 * k4);
            float4 c2 = *(const float4*)(w1 + 4 * k4);
            s0 += hv.x * a.x;  s0 += hv.y * a.y;
            s0 += hv.z * a.z;  s0 += hv.w * a.w;
            s1 += hv.x * c2.x; s1 += hv.y * c2.y;
            s1 += hv.z * c2.z; s1 += hv.w * c2.w;
        }
        gb[q * 128 + b * 2 + 0] = gx0 + s0;
        gb[q * 128 + b * 2 + 1] = gx1 + s1;
        __syncthreads();

        if (tid < 128) {
            int p = tid >> 6;
            float iv = gb[0 * 128 + b * 2 + p];
            float fv = gb[1 * 128 + b * 2 + p];
            float gv = gb[2 * 128 + b * 2 + p];
            float ov = gb[3 * 128 + b * 2 + p];
            float cn = sigf(fv) * creg + sigf(iv) * tanh_f(gv);
            float hn = sigf(ov) * tanh_f(cn);
            creg = cn; hlast = hn;
            Xout[(size_t)(t * 64 + b) * 256 + 2 * bx + p] = hn;
        }

        // grid barrier
        __syncthreads();
        __threadfence();
        if (tid == 0) {
            unsigned g = g_bar_gen;
            if (atomicAdd(&g_bar_cnt, 1u) == 127u) {
                g_bar_cnt = 0;
                __threadfence();
                g_bar_gen = g + 1;
            } else {
                while (g_bar_gen == g) { }
            }
        }
        __syncthreads();
    }

    if (tid < 128) {
        int p = tid >> 6;
        cfin[b * H_SZ + 2 * bx + p] = creg;
        hfin[b * H_SZ + 2 * bx + p] = hlast;
    }
}

// ---------------- row argmax over V ------------------------------------------
__global__ void argmax_k(const float* __restrict__ logits, float* __restrict__ outIdx)
{
    int m = blockIdx.x;
    const float* row = logits + (size_t)m * V_SZ;
    int tid = threadIdx.x;
    float bv = -__int_as_float(0x7f800000);
    int bi = 0;
    for (int n = tid; n < V_SZ; n += 256) {
        float v = row[n];
        if (v > bv) { bv = v; bi = n; }
    }
    __shared__ float sv[256];
    __shared__ int   si[256];
    sv[tid] = bv; si[tid] = bi;
    __syncthreads();
    for (int s = 128; s > 0; s >>= 1) {
        if (tid < s) {
            float ov = sv[tid + s]; int oi = si[tid + s];
            if (ov > sv[tid] || (ov == sv[tid] && oi < si[tid])) { sv[tid] = ov; si[tid] = oi; }
        }
        __syncthreads();
    }
    if (tid == 0) outIdx[m] = (float)si[0];
}

// ---------------- launch ------------------------------------------------------
extern "C" void kernel_launch(void* const* d_in, const int* in_sizes, int n_in,
                              void* d_out, int out_size)
{
    const int* inputs  = (const int*)d_in[0];
    const int* targets = (const int*)d_in[1];
    const float* enc_emb = (const float*)d_in[2];
    const float* enc_Wih = (const float*)d_in[3];
    const float* enc_Whh = (const float*)d_in[4];
    const float* enc_bih = (const float*)d_in[5];
    const float* enc_bhh = (const float*)d_in[6];
    const float* hidden0 = (const float*)d_in[7];
    const float* cell0   = (const float*)d_in[8];
    const float* dec_emb = (const float*)d_in[9];
    const float* dec_Wih = (const float*)d_in[10];
    const float* dec_Whh = (const float*)d_in[11];
    const float* dec_bih = (const float*)d_in[12];
    const float* dec_bhh = (const float*)d_in[13];
    const float* fc_W    = (const float*)d_in[14];
    const float* fc_b    = (const float*)d_in[15];
    float* out = (float*)d_out;

    float *bufA, *bufB, *gx, *hin, *hfin, *cfin;
    cudaGetSymbolAddress((void**)&bufA, g_bufA);
    cudaGetSymbolAddress((void**)&bufB, g_bufB);
    cudaGetSymbolAddress((void**)&gx,   g_gx);
    cudaGetSymbolAddress((void**)&hin,  g_hinit);
    cudaGetSymbolAddress((void**)&hfin, g_hfin);
    cudaGetSymbolAddress((void**)&cfin, g_cfin);

    cudaFuncSetAttribute(rec_k,  cudaFuncAttributeMaxDynamicSharedMemorySize, REC_SMEM_BYTES);
    cudaFuncSetAttribute(bgemm,  cudaFuncAttributeMaxDynamicSharedMemorySize, BG_SMEM);

    float* cur = bufA;
    float* nxt = bufB;

    // ---- encoder ----
    embed_k<<<M_TOT, 256>>>(inputs, enc_emb, cur, 0);
    for (int l = 0; l < 3; l++) {
        bgemm<<<148, 256, BG_SMEM>>>(cur, enc_Wih + (size_t)l * G_SZ * H_SZ,
                                     enc_bih + l * G_SZ, enc_bhh + l * G_SZ,
                                     gx, G_SZ);
        inith_k<<<B_SZ, 256>>>(hidden0 + l * H_SZ, hin, 1);
        rec_k<<<128, 256, REC_SMEM_BYTES>>>(gx, enc_Whh + (size_t)l * G_SZ * H_SZ,
                                            hin, cell0 + l * H_SZ, 1,
                                            nxt, hfin + (size_t)l * B_SZ * H_SZ,
                                            cfin + (size_t)l * B_SZ * H_SZ);
        float* tmp = cur; cur = nxt; nxt = tmp;
    }

    // ---- decoder (teacher forcing, shifted targets) ----
    embed_k<<<M_TOT, 256>>>(targets, dec_emb, cur, 1);
    for (int l = 0; l < 3; l++) {
        bgemm<<<148, 256, BG_SMEM>>>(cur, dec_Wih + (size_t)l * G_SZ * H_SZ,
                                     dec_bih + l * G_SZ, dec_bhh + l * G_SZ,
                                     gx, G_SZ);
        inith_k<<<B_SZ, 256>>>(hfin + (size_t)l * B_SZ * H_SZ, hin, 0);
        rec_k<<<128, 256, REC_SMEM_BYTES>>>(gx, dec_Whh + (size_t)l * G_SZ * H_SZ,
                                            hin, cfin + (size_t)l * B_SZ * H_SZ, 0,
                                            nxt, hfin + (size_t)l * B_SZ * H_SZ,
                                            cfin + (size_t)l * B_SZ * H_SZ);
        float* tmp = cur; cur = nxt; nxt = tmp;
    }

    // ---- FC projection to vocab (bf16 2-split mma.sync) ----
    bgemm<<<148, 256, BG_SMEM>>>(cur, fc_W, fc_b, (const float*)nullptr, out, V_SZ);

    // ---- predicted words ----
    long long need = (long long)M_TOT * V_SZ + M_TOT;
    if ((long long)out_size >= need)
        argmax_k<<<M_TOT, 256>>>(out, out + (size_t)M_TOT * V_SZ);
}